// round 9
// baseline (speedup 1.0000x reference)
#include <cuda_runtime.h>
#include <cuda_fp16.h>
#include <cstdint>

#define F_DIM    48
#define CHUNKS   12            // 48 floats = 12 float4 per node (output side)
#define N_NODES  100000
#define N_EDGES  1600000

#define SCAN_TPB   1024
#define SCAN_ELEMS (N_NODES + 1)                                // 100001
#define SCAN_NBLK  ((SCAN_ELEMS + SCAN_TPB - 1) / SCAN_TPB)     // 98

// ---------------------------------------------------------------------------
// Scratch (__device__ globals — no allocation)
// ---------------------------------------------------------------------------
__device__ int    g_count[N_NODES + 1];   // histogram -> CSR offsets -> ends
__device__ int    g_blocksums[128];       // padded to 128 for the fixup scan
__device__ int2   g_edge[N_EDGES];        // row-sorted {col, val-bits(f32)}
__device__ __half g_xh[N_NODES * F_DIM];  // x quantized to fp16 (9.6 MB)

// ---------------------------------------------------------------------------
// 1. prologue: convert x -> fp16 AND zero the histogram. One launch.
// ---------------------------------------------------------------------------
__global__ __launch_bounds__(256)
void prologue_kernel(const float4* __restrict__ x4, int n4) {
    int i = blockIdx.x * blockDim.x + threadIdx.x;
    if (i < n4) {
        float4 v = x4[i];
        __half2 h0 = __floats2half2_rn(v.x, v.y);
        __half2 h1 = __floats2half2_rn(v.z, v.w);
        uint2 packed;
        packed.x = *reinterpret_cast<unsigned int*>(&h0);
        packed.y = *reinterpret_cast<unsigned int*>(&h1);
        *reinterpret_cast<uint2*>(g_xh + (size_t)i * 4) = packed;
    }
    if (i <= N_NODES) g_count[i] = 0;
}

// ---------------------------------------------------------------------------
// 2. histogram: fire-and-forget RED, 8 edges/thread (two int4 loads)
// ---------------------------------------------------------------------------
__global__ __launch_bounds__(256)
void hist_kernel(const int* __restrict__ rows, int nE) {
    int q = blockIdx.x * blockDim.x + threadIdx.x;
    int e = q * 8;
    if (e + 7 < nE) {
        int4 r0 = *reinterpret_cast<const int4*>(rows + e);
        int4 r1 = *reinterpret_cast<const int4*>(rows + e + 4);
        atomicAdd(&g_count[r0.x + 1], 1);
        atomicAdd(&g_count[r0.y + 1], 1);
        atomicAdd(&g_count[r0.z + 1], 1);
        atomicAdd(&g_count[r0.w + 1], 1);
        atomicAdd(&g_count[r1.x + 1], 1);
        atomicAdd(&g_count[r1.y + 1], 1);
        atomicAdd(&g_count[r1.z + 1], 1);
        atomicAdd(&g_count[r1.w + 1], 1);
    } else {
        for (; e < nE; e++) atomicAdd(&g_count[__ldg(rows + e) + 1], 1);
    }
}

// ---------------------------------------------------------------------------
// 3a. block-local inclusive scan (1024 elems/block) + block sums
// ---------------------------------------------------------------------------
__global__ __launch_bounds__(SCAN_TPB)
void scan1_kernel() {
    __shared__ int buf[2][SCAN_TPB];
    int t = threadIdx.x;
    int idx = blockIdx.x * SCAN_TPB + t;
    int v = (idx < SCAN_ELEMS) ? g_count[idx] : 0;
    int src = 0;
    buf[0][t] = v;
    __syncthreads();
    #pragma unroll
    for (int off = 1; off < SCAN_TPB; off <<= 1) {
        int val = buf[src][t];
        if (t >= off) val += buf[src][t - off];
        buf[src ^ 1][t] = val;
        src ^= 1;
        __syncthreads();
    }
    if (idx < SCAN_ELEMS) g_count[idx] = buf[src][t];
    if (t == SCAN_TPB - 1) g_blocksums[blockIdx.x] = buf[src][t];
}

// ---------------------------------------------------------------------------
// 3b. fixup: parallel block-wide scan of the 98 block sums (7 log-steps),
//     then every thread adds the exclusive prefix for its block. ~1us.
// ---------------------------------------------------------------------------
__global__ __launch_bounds__(SCAN_TPB)
void scan2_kernel() {
    __shared__ int s[2][128];
    int t = threadIdx.x;

    if (t < 128) s[0][t] = (t < SCAN_NBLK) ? g_blocksums[t] : 0;
    __syncthreads();
    int src = 0;
    #pragma unroll
    for (int off = 1; off < 128; off <<= 1) {
        if (t < 128) {
            int val = s[src][t];
            if (t >= off) val += s[src][t - off];
            s[src ^ 1][t] = val;
        }
        src ^= 1;
        __syncthreads();
    }

    if (blockIdx.x == 0) return;             // block 0 needs no fixup
    int base = s[src][blockIdx.x - 1];       // exclusive prefix (broadcast)

    int idx = blockIdx.x * SCAN_TPB + t;
    if (idx < SCAN_ELEMS) g_count[idx] += base;
}

// ---------------------------------------------------------------------------
// 4. reorder: p = atomicAdd(&g_count[row], 1); 8 edges/thread -> 8
//    independent atomic->store chains in flight per thread.
//    After this kernel g_count[r] == end(r).
// ---------------------------------------------------------------------------
__global__ __launch_bounds__(256)
void reorder_kernel(const int*   __restrict__ rows,
                    const int*   __restrict__ cols,
                    const float* __restrict__ vals, int nE) {
    int q = blockIdx.x * blockDim.x + threadIdx.x;
    int e = q * 8;
    if (e + 7 < nE) {
        int r[8], cc[8], p[8];
        float vv[8];
        *reinterpret_cast<int4*>(r)      = *reinterpret_cast<const int4*>(rows + e);
        *reinterpret_cast<int4*>(r + 4)  = *reinterpret_cast<const int4*>(rows + e + 4);
        *reinterpret_cast<int4*>(cc)     = *reinterpret_cast<const int4*>(cols + e);
        *reinterpret_cast<int4*>(cc + 4) = *reinterpret_cast<const int4*>(cols + e + 4);
        *reinterpret_cast<float4*>(vv)     = *reinterpret_cast<const float4*>(vals + e);
        *reinterpret_cast<float4*>(vv + 4) = *reinterpret_cast<const float4*>(vals + e + 4);
        #pragma unroll
        for (int k = 0; k < 8; k++) p[k] = atomicAdd(&g_count[r[k]], 1);
        #pragma unroll
        for (int k = 0; k < 8; k++)
            g_edge[p[k]] = make_int2(cc[k], __float_as_int(vv[k]));
    } else {
        for (; e < nE; e++) {
            int p = atomicAdd(&g_count[__ldg(rows + e)], 1);
            g_edge[p] = make_int2(__ldg(cols + e),
                                  __float_as_int(__ldg(vals + e)));
        }
    }
}

// ---------------------------------------------------------------------------
// 5. gather: 12 lanes per node; lane c owns features [4c, 4c+4).
//    fp16 x, fp32 accumulate, w applied once, single write. No atomics.
//    start(n) = g_count[n-1] (post-reorder ends), end(n) = g_count[n].
// ---------------------------------------------------------------------------
__device__ __forceinline__ float4 load_x4h(int col, int c) {
    uint2 raw = *reinterpret_cast<const uint2*>(g_xh + (size_t)col * F_DIM + c * 4);
    __half2 h0 = *reinterpret_cast<__half2*>(&raw.x);
    __half2 h1 = *reinterpret_cast<__half2*>(&raw.y);
    float2 f0 = __half22float2(h0);
    float2 f1 = __half22float2(h1);
    return make_float4(f0.x, f0.y, f1.x, f1.y);
}

__global__ __launch_bounds__(256)
void gather_kernel(const float4* __restrict__ w4,
                   float4*       __restrict__ out4) {
    int gid = blockIdx.x * blockDim.x + threadIdx.x;
    int node = gid / CHUNKS;
    int c = gid - node * CHUNKS;
    if (node >= N_NODES) return;

    const int start = (node == 0) ? 0 : __ldg(&g_count[node - 1]);
    const int end   = __ldg(&g_count[node]);

    float4 acc = make_float4(0.f, 0.f, 0.f, 0.f);
    int e = start;
    for (; e + 3 < end; e += 4) {
        int2 m0 = __ldg(g_edge + e + 0);
        int2 m1 = __ldg(g_edge + e + 1);
        int2 m2 = __ldg(g_edge + e + 2);
        int2 m3 = __ldg(g_edge + e + 3);
        float4 a0 = load_x4h(m0.x, c);
        float4 a1 = load_x4h(m1.x, c);
        float4 a2 = load_x4h(m2.x, c);
        float4 a3 = load_x4h(m3.x, c);
        float v0 = __int_as_float(m0.y), v1 = __int_as_float(m1.y);
        float v2 = __int_as_float(m2.y), v3 = __int_as_float(m3.y);
        acc.x += v0 * a0.x + v1 * a1.x + v2 * a2.x + v3 * a3.x;
        acc.y += v0 * a0.y + v1 * a1.y + v2 * a2.y + v3 * a3.y;
        acc.z += v0 * a0.z + v1 * a1.z + v2 * a2.z + v3 * a3.z;
        acc.w += v0 * a0.w + v1 * a1.w + v2 * a2.w + v3 * a3.w;
    }
    for (; e < end; e++) {
        int2 m = __ldg(g_edge + e);
        float4 a = load_x4h(m.x, c);
        float v = __int_as_float(m.y);
        acc.x += v * a.x;
        acc.y += v * a.y;
        acc.z += v * a.z;
        acc.w += v * a.w;
    }

    float4 wv = __ldg(w4 + c);
    acc.x *= wv.x; acc.y *= wv.y; acc.z *= wv.z; acc.w *= wv.w;

    out4[(size_t)node * CHUNKS + c] = acc;
}

// ---------------------------------------------------------------------------
// Launch
// Inputs: 0 x[1,100000,48] f32 | 1 w[1,48] f32 | 2 rows[1.6M] i32
//         3 cols[1.6M] i32     | 4 vals[1.6M] f32
// Output: f32 [100000, 48]
// ---------------------------------------------------------------------------
extern "C" void kernel_launch(void* const* d_in, const int* in_sizes, int n_in,
                              void* d_out, int out_size) {
    const float* x    = (const float*)d_in[0];
    const float* w    = (const float*)d_in[1];
    const int*   rows = (const int*)  d_in[2];
    const int*   cols = (const int*)  d_in[3];
    const float* vals = (const float*)d_in[4];
    float*       out  = (float*)d_out;

    const int nE = in_sizes[2];

    // 1. prologue: x -> fp16 + zero histogram
    {
        int n4 = N_NODES * CHUNKS;                 // 1.2M float4 groups
        prologue_kernel<<<(n4 + 255) / 256, 256>>>((const float4*)x, n4);
    }
    // 2. histogram (fire-and-forget RED, 8 edges/thread)
    {
        int nq = (nE + 7) / 8;
        hist_kernel<<<(nq + 255) / 256, 256>>>(rows, nE);
    }
    // 3. scan
    scan1_kernel<<<SCAN_NBLK, SCAN_TPB>>>();
    scan2_kernel<<<SCAN_NBLK, SCAN_TPB>>>();
    // 4. reorder (atomic cursors, 8 edges/thread)
    {
        int nq = (nE + 7) / 8;
        reorder_kernel<<<(nq + 255) / 256, 256>>>(rows, cols, vals, nE);
    }
    // 5. gather (fp16 x, fp32 accumulate)
    {
        int n = N_NODES * CHUNKS;
        gather_kernel<<<(n + 255) / 256, 256>>>((const float4*)w,
                                                (float4*)out);
    }
}

// round 10
// speedup vs baseline: 1.0598x; 1.0598x over previous
#include <cuda_runtime.h>
#include <cuda_fp16.h>
#include <cstdint>

#define F_DIM    48
#define CHUNKS   12            // 48 floats = 12 float4 per node (output side)
#define N_NODES  100000
#define N_EDGES  1600000

#define SCAN_TPB   1024
#define SCAN_ELEMS (N_NODES + 1)                                // 100001
#define SCAN_NBLK  ((SCAN_ELEMS + SCAN_TPB - 1) / SCAN_TPB)     // 98

// ---------------------------------------------------------------------------
// Scratch (__device__ globals — no allocation)
// ---------------------------------------------------------------------------
__device__ int    g_count[N_NODES + 1];   // counts -> block-local scan -> cursors
__device__ int    g_blocksums[128];       // per-block totals from scan1
__device__ int2   g_edge[N_EDGES];        // row-sorted {col, val-bits(f32)}
__device__ __half g_xh[N_NODES * F_DIM];  // x quantized to fp16 (9.6 MB)

// ---------------------------------------------------------------------------
// 1. fused: convert x -> fp16 (all 1.2M threads) + histogram (first 400k
//    threads, 4 edges each, fire-and-forget RED). g_count pre-zeroed.
// ---------------------------------------------------------------------------
__global__ __launch_bounds__(256)
void convert_hist_kernel(const float4* __restrict__ x4,
                         const int*    __restrict__ rows,
                         int n4, int nE) {
    int i = blockIdx.x * blockDim.x + threadIdx.x;
    if (i < n4) {
        float4 v = x4[i];
        __half2 h0 = __floats2half2_rn(v.x, v.y);
        __half2 h1 = __floats2half2_rn(v.z, v.w);
        uint2 packed;
        packed.x = *reinterpret_cast<unsigned int*>(&h0);
        packed.y = *reinterpret_cast<unsigned int*>(&h1);
        *reinterpret_cast<uint2*>(g_xh + (size_t)i * 4) = packed;
    }
    int e = i * 4;
    if (e + 3 < nE) {
        int4 r = *reinterpret_cast<const int4*>(rows + e);
        atomicAdd(&g_count[r.x + 1], 1);
        atomicAdd(&g_count[r.y + 1], 1);
        atomicAdd(&g_count[r.z + 1], 1);
        atomicAdd(&g_count[r.w + 1], 1);
    } else if (e < nE) {
        for (; e < nE; e++) atomicAdd(&g_count[rows[e] + 1], 1);
    }
}

// ---------------------------------------------------------------------------
// 2. scan1: block-local inclusive scan (1024 elems/block) + block sums.
//    NO global fixup pass — consumers add the block prefix themselves.
// ---------------------------------------------------------------------------
__global__ __launch_bounds__(SCAN_TPB)
void scan1_kernel() {
    __shared__ int buf[2][SCAN_TPB];
    int t = threadIdx.x;
    int idx = blockIdx.x * SCAN_TPB + t;
    int v = (idx < SCAN_ELEMS) ? g_count[idx] : 0;
    int src = 0;
    buf[0][t] = v;
    __syncthreads();
    #pragma unroll
    for (int off = 1; off < SCAN_TPB; off <<= 1) {
        int val = buf[src][t];
        if (t >= off) val += buf[src][t - off];
        buf[src ^ 1][t] = val;
        src ^= 1;
        __syncthreads();
    }
    if (idx < SCAN_ELEMS) g_count[idx] = buf[src][t];
    if (t == SCAN_TPB - 1) g_blocksums[blockIdx.x] = buf[src][t];
}

// ---------------------------------------------------------------------------
// Helper: scan the <=98 block sums into smem EXCLUSIVE prefixes.
// Call from every block of reorder/gather; cost ~300cyc, fully parallel.
// s_bpre[b] = sum of blocksums[0..b-1].
// ---------------------------------------------------------------------------
__device__ __forceinline__ void load_block_prefixes(int* s_bpre, int t) {
    __shared__ int tmp[2][128];
    if (t < 128) tmp[0][t] = (t < SCAN_NBLK) ? g_blocksums[t] : 0;
    __syncthreads();
    int src = 0;
    #pragma unroll
    for (int off = 1; off < 128; off <<= 1) {
        if (t < 128) {
            int val = tmp[src][t];
            if (t >= off) val += tmp[src][t - off];
            tmp[src ^ 1][t] = val;
        }
        src ^= 1;
        __syncthreads();
    }
    if (t < 128) s_bpre[t] = (t == 0) ? 0 : tmp[src][t - 1];
    __syncthreads();
}

// ---------------------------------------------------------------------------
// 3. reorder: p = atomicAdd(&g_count[row],1) + bprefix[row>>10].
//    4 edges/thread (4 independent atomic chains). After this kernel,
//    g_count[r] = local end(r); global end(r) = g_count[r] + bprefix[r>>10].
// ---------------------------------------------------------------------------
__global__ __launch_bounds__(256)
void reorder_kernel(const int*   __restrict__ rows,
                    const int*   __restrict__ cols,
                    const float* __restrict__ vals, int nE) {
    __shared__ int s_bpre[128];
    load_block_prefixes(s_bpre, threadIdx.x);

    int q = blockIdx.x * blockDim.x + threadIdx.x;
    int e = q * 4;
    if (e + 3 < nE) {
        int4   r  = *reinterpret_cast<const int4*>(rows + e);
        int4   cc = *reinterpret_cast<const int4*>(cols + e);
        float4 vv = *reinterpret_cast<const float4*>(vals + e);
        int p0 = atomicAdd(&g_count[r.x], 1) + s_bpre[r.x >> 10];
        int p1 = atomicAdd(&g_count[r.y], 1) + s_bpre[r.y >> 10];
        int p2 = atomicAdd(&g_count[r.z], 1) + s_bpre[r.z >> 10];
        int p3 = atomicAdd(&g_count[r.w], 1) + s_bpre[r.w >> 10];
        g_edge[p0] = make_int2(cc.x, __float_as_int(vv.x));
        g_edge[p1] = make_int2(cc.y, __float_as_int(vv.y));
        g_edge[p2] = make_int2(cc.z, __float_as_int(vv.z));
        g_edge[p3] = make_int2(cc.w, __float_as_int(vv.w));
    } else if (e < nE) {
        for (; e < nE; e++) {
            int r = rows[e];
            int p = atomicAdd(&g_count[r], 1) + s_bpre[r >> 10];
            g_edge[p] = make_int2(cols[e], __float_as_int(vals[e]));
        }
    }
}

// ---------------------------------------------------------------------------
// 4. gather: 12 lanes per node; lane c owns features [4c, 4c+4).
//    fp16 x, fp32 accumulate, w applied once, single write. No atomics.
//    start(n) = g_count[n-1] + bpre[(n-1)>>10], end(n) = g_count[n] + bpre[n>>10]
// ---------------------------------------------------------------------------
__device__ __forceinline__ float4 load_x4h(int col, int c) {
    uint2 raw = *reinterpret_cast<const uint2*>(g_xh + (size_t)col * F_DIM + c * 4);
    __half2 h0 = *reinterpret_cast<__half2*>(&raw.x);
    __half2 h1 = *reinterpret_cast<__half2*>(&raw.y);
    float2 f0 = __half22float2(h0);
    float2 f1 = __half22float2(h1);
    return make_float4(f0.x, f0.y, f1.x, f1.y);
}

__global__ __launch_bounds__(256)
void gather_kernel(const float4* __restrict__ w4,
                   float4*       __restrict__ out4) {
    __shared__ int s_bpre[128];
    load_block_prefixes(s_bpre, threadIdx.x);

    int gid = blockIdx.x * blockDim.x + threadIdx.x;
    int node = gid / CHUNKS;
    int c = gid - node * CHUNKS;
    if (node >= N_NODES) return;

    int start, end;
    end = __ldg(&g_count[node]) + s_bpre[node >> 10];
    if (node == 0) start = 0;
    else           start = __ldg(&g_count[node - 1]) + s_bpre[(node - 1) >> 10];

    float4 acc = make_float4(0.f, 0.f, 0.f, 0.f);
    int e = start;
    for (; e + 3 < end; e += 4) {
        int2 m0 = __ldg(g_edge + e + 0);
        int2 m1 = __ldg(g_edge + e + 1);
        int2 m2 = __ldg(g_edge + e + 2);
        int2 m3 = __ldg(g_edge + e + 3);
        float4 a0 = load_x4h(m0.x, c);
        float4 a1 = load_x4h(m1.x, c);
        float4 a2 = load_x4h(m2.x, c);
        float4 a3 = load_x4h(m3.x, c);
        float v0 = __int_as_float(m0.y), v1 = __int_as_float(m1.y);
        float v2 = __int_as_float(m2.y), v3 = __int_as_float(m3.y);
        acc.x += v0 * a0.x + v1 * a1.x + v2 * a2.x + v3 * a3.x;
        acc.y += v0 * a0.y + v1 * a1.y + v2 * a2.y + v3 * a3.y;
        acc.z += v0 * a0.z + v1 * a1.z + v2 * a2.z + v3 * a3.z;
        acc.w += v0 * a0.w + v1 * a1.w + v2 * a2.w + v3 * a3.w;
    }
    for (; e < end; e++) {
        int2 m = __ldg(g_edge + e);
        float4 a = load_x4h(m.x, c);
        float v = __int_as_float(m.y);
        acc.x += v * a.x;
        acc.y += v * a.y;
        acc.z += v * a.z;
        acc.w += v * a.w;
    }

    float4 wv = __ldg(w4 + c);
    acc.x *= wv.x; acc.y *= wv.y; acc.z *= wv.z; acc.w *= wv.w;

    out4[(size_t)node * CHUNKS + c] = acc;
}

// ---------------------------------------------------------------------------
// Launch: memset -> fused(convert+hist) -> scan1 -> reorder -> gather
// Inputs: 0 x[1,100000,48] f32 | 1 w[1,48] f32 | 2 rows[1.6M] i32
//         3 cols[1.6M] i32     | 4 vals[1.6M] f32
// Output: f32 [100000, 48]
// ---------------------------------------------------------------------------
extern "C" void kernel_launch(void* const* d_in, const int* in_sizes, int n_in,
                              void* d_out, int out_size) {
    const float* x    = (const float*)d_in[0];
    const float* w    = (const float*)d_in[1];
    const int*   rows = (const int*)  d_in[2];
    const int*   cols = (const int*)  d_in[3];
    const float* vals = (const float*)d_in[4];
    float*       out  = (float*)d_out;

    const int nE = in_sizes[2];
    const int n4 = N_NODES * CHUNKS;               // 1.2M float4 groups

    // 0. zero histogram
    void* count_ptr = nullptr;
    cudaGetSymbolAddress(&count_ptr, g_count);
    cudaMemsetAsync(count_ptr, 0, (N_NODES + 1) * sizeof(int), 0);

    // 1. fused convert + histogram
    convert_hist_kernel<<<(n4 + 255) / 256, 256>>>((const float4*)x, rows,
                                                   n4, nE);
    // 2. block-local scan
    scan1_kernel<<<SCAN_NBLK, SCAN_TPB>>>();
    // 3. reorder
    {
        int nq = (nE + 3) / 4;
        reorder_kernel<<<(nq + 255) / 256, 256>>>(rows, cols, vals, nE);
    }
    // 4. gather
    gather_kernel<<<(n4 + 255) / 256, 256>>>((const float4*)w, (float4*)out);
}